// round 14
// baseline (speedup 1.0000x reference)
#include <cuda_runtime.h>
#include <cuda_bf16.h>
#include <cstdint>
#include <cstddef>

// Problem dims (fixed by dataset)
#define BB 32
#define SS 1024
#define II 512
#define HH 512
#define NB 128        // persistent blocks in recurrence
#define NT 256        // threads per recurrence block (8 warps)
#define KT 192        // k handled by tensor path (bf16 hi/lo)
#define KF 320        // k handled by fp32 path (k in [192,512))

// ---------------------------------------------------------------------------
// Scratch (device globals: allocation-free per harness rules)
__device__ float g_G[(size_t)SS * 2048 * BB];          // [s][n][b]
__device__ float g_Hist[(size_t)(SS / 2) * BB * HH];   // [s'][b][h]
__device__ __nv_bfloat16 g_hbf[2][2][BB][HH];          // [buf][hi/lo][b][k] (k<192 used)
__device__ float g_hf32[2][HH][BB];                    // [buf][k][b]       (k>=192 used)
__device__ unsigned g_cnt;
__device__ volatile unsigned g_gen;
// bf16 hi/lo operands for tensor-core GEMMs
__device__ __nv_bfloat16 g_xh[(size_t)SS * BB * II];   // [m=s*32+b][i]
__device__ __nv_bfloat16 g_xl[(size_t)SS * BB * II];
__device__ __nv_bfloat16 g_Wh[2048 * II];              // [n=g*512+h][i]
__device__ __nv_bfloat16 g_Wl[2048 * II];
__device__ __nv_bfloat16 g_Rh[2048 * HH];              // [n=g*512+h][k]
__device__ __nv_bfloat16 g_Rl[2048 * HH];

__device__ __forceinline__ float sigf(float x) { return 1.0f / (1.0f + expf(-x)); }

// Packed fp32x2 helpers
__device__ __forceinline__ void ffma2(unsigned long long& d,
                                      unsigned long long a,
                                      unsigned long long b) {
    asm("fma.rn.f32x2 %0, %1, %2, %0;" : "+l"(d) : "l"(a), "l"(b));
}
__device__ __forceinline__ unsigned long long splat2(float x) {
    unsigned long long r;
    asm("mov.b64 %0, {%1, %1};" : "=l"(r) : "f"(x));
    return r;
}
__device__ __forceinline__ float2 unpack2(unsigned long long v) {
    float2 f;
    asm("mov.b64 {%0, %1}, %2;" : "=f"(f.x), "=f"(f.y) : "l"(v));
    return f;
}

// Base-ISA async-copy + HMMA + ldmatrix helpers (compute_100-safe)
__device__ __forceinline__ uint32_t smem_u32(const void* p) {
    uint32_t a;
    asm("{ .reg .u64 t; cvta.to.shared.u64 t, %1; cvt.u32.u64 %0, t; }"
        : "=r"(a) : "l"(p));
    return a;
}
__device__ __forceinline__ void cpa16(uint32_t dst, const void* src) {
    asm volatile("cp.async.cg.shared.global [%0], [%1], 16;"
                 :: "r"(dst), "l"(src) : "memory");
}
__device__ __forceinline__ void cpa_commit() {
    asm volatile("cp.async.commit_group;" ::: "memory");
}
__device__ __forceinline__ void cpa_wait0() {
    asm volatile("cp.async.wait_group 0;" ::: "memory");
}
__device__ __forceinline__ void mma_bf16(float* d, const uint32_t* a,
                                         const uint32_t* b) {
    asm volatile(
        "mma.sync.aligned.m16n8k16.row.col.f32.bf16.bf16.f32 "
        "{%0,%1,%2,%3}, {%4,%5,%6,%7}, {%8,%9}, {%0,%1,%2,%3};"
        : "+f"(d[0]), "+f"(d[1]), "+f"(d[2]), "+f"(d[3])
        : "r"(a[0]), "r"(a[1]), "r"(a[2]), "r"(a[3]), "r"(b[0]), "r"(b[1]));
}
__device__ __forceinline__ void ldsm4(uint32_t* r, uint32_t addr) {
    asm volatile("ldmatrix.sync.aligned.m8n8.x4.shared.b16 {%0,%1,%2,%3}, [%4];"
                 : "=r"(r[0]), "=r"(r[1]), "=r"(r[2]), "=r"(r[3]) : "r"(addr));
}

// ---------------------------------------------------------------------------
// Prepass: x -> g_xh/g_xl ([m][i]),  W -> g_Wh/g_Wl,  R -> g_Rh/g_Rl.
__global__ void __launch_bounds__(256) convert_prepass(
    const float* __restrict__ x,
    const float* __restrict__ Wz, const float* __restrict__ Wi,
    const float* __restrict__ Wf, const float* __restrict__ Wo,
    const float* __restrict__ Rz, const float* __restrict__ Ri,
    const float* __restrict__ Rf, const float* __restrict__ Ro)
{
    const int total = 4194304 + 262144 + 262144;   // float4 groups
    for (int t = blockIdx.x * blockDim.x + threadIdx.x; t < total;
         t += gridDim.x * blockDim.x) {
        float4 v;
        uint2* oh;
        uint2* ol;
        size_t oidx;
        if (t < 4194304) {                 // x part
            const int b = t >> 17, s = (t >> 7) & 1023, i4 = t & 127;
            v = ((const float4*)x)[(size_t)t];
            const int m = s * 32 + b;
            oidx = (size_t)m * 128 + i4;
            oh = (uint2*)g_xh; ol = (uint2*)g_xl;
        } else if (t < 4194304 + 262144) { // W part
            const int u = t - 4194304;
            const int n = u >> 7, i4 = u & 127;
            const int g = n >> 9, hr = n & 511;
            const float* Wg = (g == 0) ? Wz : (g == 1) ? Wi : (g == 2) ? Wf : Wo;
            v = ((const float4*)Wg)[(size_t)hr * 128 + i4];
            oidx = (size_t)n * 128 + i4;
            oh = (uint2*)g_Wh; ol = (uint2*)g_Wl;
        } else {                           // R part
            const int u = t - 4194304 - 262144;
            const int n = u >> 7, i4 = u & 127;
            const int g = n >> 9, hr = n & 511;
            const float* Rg = (g == 0) ? Rz : (g == 1) ? Ri : (g == 2) ? Rf : Ro;
            v = ((const float4*)Rg)[(size_t)hr * 128 + i4];
            oidx = (size_t)n * 128 + i4;
            oh = (uint2*)g_Rh; ol = (uint2*)g_Rl;
        }
        unsigned short h[4], l[4];
        const float* f = (const float*)&v;
#pragma unroll
        for (int j = 0; j < 4; j++) {
            __nv_bfloat16 bh = __float2bfloat16_rn(f[j]);
            float r = f[j] - __bfloat162float(bh);
            __nv_bfloat16 bl = __float2bfloat16_rn(r);
            h[j] = __bfloat16_as_ushort(bh);
            l[j] = __bfloat16_as_ushort(bl);
        }
        uint2 uh, ul;
        uh.x = (uint32_t)h[0] | ((uint32_t)h[1] << 16);
        uh.y = (uint32_t)h[2] | ((uint32_t)h[3] << 16);
        ul.x = (uint32_t)l[0] | ((uint32_t)l[1] << 16);
        ul.y = (uint32_t)l[2] | ((uint32_t)l[3] << 16);
        oh[oidx] = uh;
        ol[oidx] = ul;
    }
}

// ---------------------------------------------------------------------------
// Tensor-core input GEMM (HMMA, unchanged from R10 pass): G = X·W^T + bias.
#define IG_PITCH 72
#define IG_ARR   (128 * IG_PITCH)
#define IG_BUF   (4 * IG_ARR)
#define IG_SMEM  (2 * IG_BUF * 2)
__global__ void __launch_bounds__(256, 1) input_gemm_tc(
    const float* __restrict__ bz, const float* __restrict__ bi,
    const float* __restrict__ bf, const float* __restrict__ bo)
{
    extern __shared__ __nv_bfloat16 smb[];
    const uint32_t sb0 = smem_u32(smb);
    const int tid = threadIdx.x;
    const int wid = tid >> 5, lane = tid & 31;
    const int g = lane >> 2, t = lane & 3;
    const int wm = wid >> 2, wn = wid & 3;
    const int bx = blockIdx.x, by = blockIdx.y;
    const int n0 = bx * 128, m0 = by * 128;

    auto stage = [&](int c, int buf) {
        const uint32_t base = sb0 + (uint32_t)buf * (IG_BUF * 2);
        const uint4* srcA_h = (const uint4*)g_xh + (size_t)m0 * 64 + c * 8;
        const uint4* srcA_l = (const uint4*)g_xl + (size_t)m0 * 64 + c * 8;
        const uint4* srcB_h = (const uint4*)g_Wh + (size_t)n0 * 64 + c * 8;
        const uint4* srcB_l = (const uint4*)g_Wl + (size_t)n0 * 64 + c * 8;
        const uint4* srcs[4] = { srcA_h, srcA_l, srcB_h, srcB_l };
#pragma unroll
        for (int a = 0; a < 4; a++) {
#pragma unroll
            for (int i = 0; i < 4; i++) {
                const int idx = i * 256 + tid;
                const int r = idx >> 3, u = idx & 7;
                cpa16(base + (uint32_t)(a * (IG_ARR * 2) + r * (IG_PITCH * 2) + u * 16),
                      srcs[a] + (size_t)r * 64 + u);
            }
        }
        cpa_commit();
    };

    float acc[4][4][4];
#pragma unroll
    for (int mi = 0; mi < 4; mi++)
#pragma unroll
        for (int ni = 0; ni < 4; ni++)
#pragma unroll
            for (int r = 0; r < 4; r++) acc[mi][ni][r] = 0.0f;

    stage(0, 0);

    for (int c = 0; c < 8; c++) {
        cpa_wait0();
        __syncthreads();
        if (c + 1 < 8) stage(c + 1, (c + 1) & 1);

        const __nv_bfloat16* Ah = smb + (size_t)(c & 1) * IG_BUF;
        const __nv_bfloat16* Al = Ah + IG_ARR;
        const __nv_bfloat16* Bh = Ah + 2 * IG_ARR;
        const __nv_bfloat16* Bl = Ah + 3 * IG_ARR;

#pragma unroll
        for (int ks = 0; ks < 4; ks++) {
            const int k0 = ks * 16;
            uint32_t ah[4][4], al[4][4], bh[4][2], bl[4][2];
#pragma unroll
            for (int mi = 0; mi < 4; mi++) {
                const int r0 = wm * 64 + mi * 16 + g;
                const int cA = k0 + 2 * t;
                ah[mi][0] = *(const uint32_t*)(Ah + r0 * IG_PITCH + cA);
                ah[mi][1] = *(const uint32_t*)(Ah + (r0 + 8) * IG_PITCH + cA);
                ah[mi][2] = *(const uint32_t*)(Ah + r0 * IG_PITCH + cA + 8);
                ah[mi][3] = *(const uint32_t*)(Ah + (r0 + 8) * IG_PITCH + cA + 8);
                al[mi][0] = *(const uint32_t*)(Al + r0 * IG_PITCH + cA);
                al[mi][1] = *(const uint32_t*)(Al + (r0 + 8) * IG_PITCH + cA);
                al[mi][2] = *(const uint32_t*)(Al + r0 * IG_PITCH + cA + 8);
                al[mi][3] = *(const uint32_t*)(Al + (r0 + 8) * IG_PITCH + cA + 8);
            }
#pragma unroll
            for (int ni = 0; ni < 4; ni++) {
                const int rB = wn * 32 + ni * 8 + g;
                const int cB = k0 + 2 * t;
                bh[ni][0] = *(const uint32_t*)(Bh + rB * IG_PITCH + cB);
                bh[ni][1] = *(const uint32_t*)(Bh + rB * IG_PITCH + cB + 8);
                bl[ni][0] = *(const uint32_t*)(Bl + rB * IG_PITCH + cB);
                bl[ni][1] = *(const uint32_t*)(Bl + rB * IG_PITCH + cB + 8);
            }
#pragma unroll
            for (int mi = 0; mi < 4; mi++)
#pragma unroll
                for (int ni = 0; ni < 4; ni++) {
                    mma_bf16(acc[mi][ni], ah[mi], bh[ni]);
                    mma_bf16(acc[mi][ni], ah[mi], bl[ni]);
                    mma_bf16(acc[mi][ni], al[mi], bh[ni]);
                }
        }
        __syncthreads();
    }

    const int gate = bx >> 2;
    const float* bias = (gate == 0) ? bz : (gate == 1) ? bi : (gate == 2) ? bf : bo;
    const int nlb = (bx & 3) * 128;
#pragma unroll
    for (int mi = 0; mi < 4; mi++) {
        const int row0 = m0 + wm * 64 + mi * 16 + g;
        const int row1 = row0 + 8;
        const int s0 = row0 >> 5, b0 = row0 & 31;
        const int s1 = row1 >> 5, b1 = row1 & 31;
#pragma unroll
        for (int ni = 0; ni < 4; ni++) {
            const int nl = wn * 32 + ni * 8 + 2 * t;
            const int n = n0 + nl;
            const float bv0 = bias[nlb + nl], bv1 = bias[nlb + nl + 1];
            g_G[((size_t)s0 * 2048 + n) * BB + b0]     = acc[mi][ni][0] + bv0;
            g_G[((size_t)s0 * 2048 + n + 1) * BB + b0] = acc[mi][ni][1] + bv1;
            g_G[((size_t)s1 * 2048 + n) * BB + b1]     = acc[mi][ni][2] + bv0;
            g_G[((size_t)s1 * 2048 + n + 1) * BB + b1] = acc[mi][ni][3] + bv1;
        }
    }
}

// ---------------------------------------------------------------------------
// HYBRID tensor+fp32 persistent recurrence. 128 blocks x 256 threads (8 warps),
// 1 block/SM.  Block = (hcols jc=(bid>>1)*8, b-half b0g=(bid&1)*16).
// Warps 0-3 (one per SMSP): bf16 hi/lo mma over k in [0,192).
// Warps 4-7 (one per SMSP): fp32 FFMA2 outer products over k in [192,512).
// h staging via __ldcg (proven R6-R9 mechanism; cp.async removed as the one
// novel suspect after two container failures on the cp.async variant).
//
// smem byte layout:
#define RS_HO 0                     // tensor R hi: 32 x pitch400 = 12800
#define RS_LO 12800                 // tensor R lo: 12800
#define HS_HO 25600                 // tensor h hi: 16 x 400 = 6400
#define HS_LO 32000                 // tensor h lo: 6400
#define RF_O  38400                 // fp32 R: [320][36] f32 = 46080
#define HF_O  84480                 // fp32 h: [320][20] f32 = 25600
#define RED_O 110080                // red: 8 x 32 x 18 f32 = 18432
#define CSM_O 128512                // 128 f32
#define BRS_O 129024                // 32 f32
#define RC_SMEM 129152
__global__ void __launch_bounds__(NT, 1) recurrence(
    const float* __restrict__ Rz, const float* __restrict__ Ri,
    const float* __restrict__ Rf, const float* __restrict__ Ro,
    const float* __restrict__ brz, const float* __restrict__ bri,
    const float* __restrict__ brf, const float* __restrict__ bro)
{
    extern __shared__ char smc[];
    float* red = (float*)(smc + RED_O);
    float* csm = (float*)(smc + CSM_O);
    float* brs = (float*)(smc + BRS_O);
    float* rfp = (float*)(smc + RF_O);
    float* hfp = (float*)(smc + HF_O);
    const uint32_t sbb = smem_u32(smc);

    const int tid = threadIdx.x;
    const int bid = blockIdx.x;
    const int jc  = (bid >> 1) * 8;
    const int b0g = (bid & 1) * 16;
    const int w = tid >> 5, lane = tid & 31;

    __shared__ unsigned s_base;
    if (tid == 0) s_base = g_gen;     // consistent snapshot (see R1 notes)

    // --- One-time staging ---
    // Tensor R (k<192): rows m = g*8+c -> n = g*512+jc+c; hi+lo, pitch 400 B.
    for (int i = 0; i < 6; i++) {
        const int idx = i * 256 + tid;            // 1536 uint4
        const int part = idx / 768, rest = idx % 768;
        const int m = rest / 24, u = rest % 24;
        const int n = (m >> 3) * 512 + jc + (m & 7);
        const uint4 v = *((const uint4*)(part ? g_Rl : g_Rh) + (size_t)n * 64 + u);
        *(uint4*)(smc + (part ? RS_LO : RS_HO) + m * 400 + u * 16) = v;
    }
    // fp32 R (k>=192), transposed: rfp[kf*36 + m] = Rg[row][192+kf].
    // NOTE: Rg is the per-gate 512x512 tensor -> index by LOCAL row jc+(m&7).
    for (int i = 0; i < 10; i++) {
        const int idx = i * 256 + tid;            // 2560 float4 reads
        const int m = idx / 80, q = idx % 80;
        const int g = m >> 3;
        const int row = jc + (m & 7);             // local row within Rg
        const float* Rg = (g == 0) ? Rz : (g == 1) ? Ri : (g == 2) ? Rf : Ro;
        const float4 v = *(const float4*)(Rg + (size_t)row * 512 + 192 + q * 4);
        rfp[(q * 4 + 0) * 36 + m] = v.x;
        rfp[(q * 4 + 1) * 36 + m] = v.y;
        rfp[(q * 4 + 2) * 36 + m] = v.z;
        rfp[(q * 4 + 3) * 36 + m] = v.w;
    }
    if (tid < 32) {
        const int g = tid >> 3, c = tid & 7;
        const float* bg = (g == 0) ? brz : (g == 1) ? bri : (g == 2) ? brf : bro;
        brs[tid] = bg[jc + c];
    }
    if (tid < 128) csm[tid] = 0.0f;
    __syncthreads();
    const unsigned base = s_base;

    // ldmatrix lane-address components (byte offsets, pitch 400)
    const int arow = (lane & 15) * 400;
    const int akad = (lane >> 4) * 16;
    const int brow = (((lane >> 4) & 1) * 8 + (lane & 7)) * 400;
    const int bkad = ((lane >> 3) & 1) * 16;
    // fp32 lane roles: 4n x 4b microtile
    const int n_grp = lane & 7;       // n-local = 4*n_grp + nn
    const int b_grp = lane >> 3;      // b-local = 4*b_grp + bb
    // cell roles (threads 0..127)
    const int c_ = (tid >> 4) & 7;
    const int b_ = tid & 15;
    const int grp = lane >> 2, qp = lane & 3;
    const bool tensor_h = (jc < KT);  // uniform per block

    float gv0 = 0.f, gv1 = 0.f, gv2 = 0.f, gv3 = 0.f;
    if (tid < 128) {
        gv0 = g_G[(0 * 512 + jc + c_) * BB + b0g + b_];
        gv1 = g_G[(1 * 512 + jc + c_) * BB + b0g + b_];
        gv2 = g_G[(2 * 512 + jc + c_) * BB + b0g + b_];
        gv3 = g_G[(3 * 512 + jc + c_) * BB + b0g + b_];
    }

    float histv = 0.0f;
    int   hist_idx = -1;

    for (int s = 0; s < SS; ++s) {
        // --- Stage h (plain __ldcg loads; L2-coherent) ---
        if (s == 0) {
            const uint4 z4 = make_uint4(0, 0, 0, 0);
            for (int i = 0; i < 4; i++) {              // 800 uint4 HS
                const int idx = i * 256 + tid;
                if (idx < 800) *(uint4*)(smc + HS_HO + idx * 16) = z4;
            }
            for (int i = 0; i < 7; i++) {              // 1600 uint4 HF
                const int idx = i * 256 + tid;
                if (idx < 1600) *(uint4*)(smc + HF_O + idx * 16) = z4;
            }
        } else {
            const int pb = (s - 1) & 1;
            // tensor h (k<192): 768 uint4
            for (int i = 0; i < 3; i++) {
                const int idx = i * 256 + tid;
                const int part = idx / 384, rest = idx % 384;
                const int r = rest / 24, u = rest % 24;
                const uint4 v = __ldcg((const uint4*)g_hbf +
                    ((size_t)((pb * 2 + part) * 32 + b0g + r)) * 64 + u);
                *(uint4*)(smc + (part ? HS_LO : HS_HO) + r * 400 + u * 16) = v;
            }
            // fp32 h (k>=192): 1280 uint4
            for (int i = 0; i < 5; i++) {
                const int idx = i * 256 + tid;
                const int kf = idx >> 2, v4 = idx & 3;
                const uint4 hv = __ldcg((const uint4*)&g_hf32[pb][192 + kf][b0g + 4 * v4]);
                *(uint4*)(smc + HF_O + kf * 80 + v4 * 16) = hv;
            }
        }
        __syncthreads();

        if (w < 4) {
            // ---- Tensor path: warp w covers k in [w*48, w*48+48), 3 ks.
            float acc[2][2][4];
#pragma unroll
            for (int mi = 0; mi < 2; mi++)
#pragma unroll
                for (int ni = 0; ni < 2; ni++)
#pragma unroll
                    for (int r = 0; r < 4; r++) acc[mi][ni][r] = 0.0f;

#pragma unroll
            for (int ks = 0; ks < 3; ks++) {
                const int kbb = (w * 48 + ks * 16) * 2;   // byte offset
                uint32_t Ah0[4], Ah1[4], Al0[4], Al1[4], Bh[4], Bl[4];
                ldsm4(Ah0, sbb + RS_HO + arow + kbb + akad);
                ldsm4(Ah1, sbb + RS_HO + 6400 + arow + kbb + akad);
                ldsm4(Al0, sbb + RS_LO + arow + kbb + akad);
                ldsm4(Al1, sbb + RS_LO + 6400 + arow + kbb + akad);
                ldsm4(Bh,  sbb + HS_HO + brow + kbb + bkad);
                ldsm4(Bl,  sbb + HS_LO + brow + kbb + bkad);
                mma_bf16(acc[0][0], Ah0, Bh);  mma_bf16(acc[0][1], Ah0, Bh + 2);
                mma_bf16(acc[1][0], Ah1, Bh);  mma_bf16(acc[1][1], Ah1, Bh + 2);
                mma_bf16(acc[0][0], Ah0, Bl);  mma_bf16(acc[0][1], Ah0, Bl + 2);
                mma_bf16(acc[1][0], Ah1, Bl);  mma_bf16(acc[1][1], Ah1, Bl + 2);
                mma_bf16(acc[0][0], Al0, Bh);  mma_bf16(acc[0][1], Al0, Bh + 2);
                mma_bf16(acc[1][0], Al1, Bh);  mma_bf16(acc[1][1], Al1, Bh + 2);
            }
            // Partials -> red[w][n 0..31][b 0..15] pitch 18
#pragma unroll
            for (int mi = 0; mi < 2; mi++)
#pragma unroll
                for (int ni = 0; ni < 2; ni++) {
                    const int row = mi * 16 + grp;
                    const int col = ni * 8 + qp * 2;
                    *(float2*)&red[(w * 32 + row) * 18 + col] =
                        make_float2(acc[mi][ni][0], acc[mi][ni][1]);
                    *(float2*)&red[(w * 32 + row + 8) * 18 + col] =
                        make_float2(acc[mi][ni][2], acc[mi][ni][3]);
                }
        } else {
            // ---- fp32 path: warp w covers kf in [(w-4)*80, +80).
            const int kf0 = (w - 4) * 80;
            unsigned long long a2[4][2];
#pragma unroll
            for (int nn = 0; nn < 4; nn++) { a2[nn][0] = 0ULL; a2[nn][1] = 0ULL; }

            const float* rp = rfp + (size_t)kf0 * 36 + 4 * n_grp;
            const float* hp = hfp + (size_t)kf0 * 20 + 4 * b_grp;
#pragma unroll 4
            for (int kf = 0; kf < 80; kf++) {
                const float4 rv = *(const float4*)(rp);
                const ulonglong2 hv = *(const ulonglong2*)(hp);
                unsigned long long s0 = splat2(rv.x);
                unsigned long long s1 = splat2(rv.y);
                unsigned long long s2 = splat2(rv.z);
                unsigned long long s3 = splat2(rv.w);
                ffma2(a2[0][0], s0, hv.x);  ffma2(a2[0][1], s0, hv.y);
                ffma2(a2[1][0], s1, hv.x);  ffma2(a2[1][1], s1, hv.y);
                ffma2(a2[2][0], s2, hv.x);  ffma2(a2[2][1], s2, hv.y);
                ffma2(a2[3][0], s3, hv.x);  ffma2(a2[3][1], s3, hv.y);
                rp += 36; hp += 20;
            }
#pragma unroll
            for (int nn = 0; nn < 4; nn++)
#pragma unroll
                for (int p = 0; p < 2; p++) {
                    const float2 f = unpack2(a2[nn][p]);
                    *(float2*)&red[(w * 32 + 4 * n_grp + nn) * 18 + 4 * b_grp + 2 * p] = f;
                }
        }
        __syncthreads();

        // Gate phase (threads 0..127): cell (hcol c_, batch b_).
        if (tid < 128) {
            float pz = gv0 + brs[0 + c_];
            float pi_ = gv1 + brs[8 + c_];
            float pf = gv2 + brs[16 + c_];
            float po = gv3 + brs[24 + c_];
#pragma unroll
            for (int q = 0; q < 8; q++) {
                pz  += red[(q * 32 + 0 + c_) * 18 + b_];
                pi_ += red[(q * 32 + 8 + c_) * 18 + b_];
                pf  += red[(q * 32 + 16 + c_) * 18 + b_];
                po  += red[(q * 32 + 24 + c_) * 18 + b_];
            }
            const float z  = tanhf(pz);
            const float iv = sigf(pi_);
            const float f  = sigf(pf);
            const float o  = sigf(po);
            const float cc = fmaf(f, csm[tid], z * iv);
            csm[tid] = cc;
            const float h = o * tanhf(cc);
            if (tensor_h) {
                const __nv_bfloat16 hh = __float2bfloat16_rn(h);
                const __nv_bfloat16 hl = __float2bfloat16_rn(h - __bfloat162float(hh));
                g_hbf[s & 1][0][b0g + b_][jc + c_] = hh;
                g_hbf[s & 1][1][b0g + b_][jc + c_] = hl;
            } else {
                g_hf32[s & 1][jc + c_][b0g + b_] = h;
            }
            histv = h;
            hist_idx = (s >= SS / 2)
                     ? (int)(((size_t)(s - SS / 2) * BB + b0g + b_) * HH + jc + c_)
                     : -1;
        }

        // Prefetch next step's G, grid barrier, then deferred Hist store.
        if (s < SS - 1) {
            float t0 = 0.f, t1 = 0.f, t2 = 0.f, t3 = 0.f;
            if (tid < 128) {
                const float* Gn = g_G + (size_t)(s + 1) * (2048 * BB);
                t0 = Gn[(0 * 512 + jc + c_) * BB + b0g + b_];
                t1 = Gn[(1 * 512 + jc + c_) * BB + b0g + b_];
                t2 = Gn[(2 * 512 + jc + c_) * BB + b0g + b_];
                t3 = Gn[(3 * 512 + jc + c_) * BB + b0g + b_];
            }
            __threadfence();
            __syncthreads();
            if (tid == 0) {
                const unsigned tgt = base + (unsigned)s + 1u;
                if (atomicAdd(&g_cnt, 1u) == NB - 1u) {
                    atomicExch(&g_cnt, 0u);
                    __threadfence();
                    g_gen = tgt;
                } else {
                    while ((int)(g_gen - tgt) < 0) __nanosleep(32);
                    __threadfence();
                }
            }
            __syncthreads();
            if (hist_idx >= 0) g_Hist[hist_idx] = histv;
            gv0 = t0; gv1 = t1; gv2 = t2; gv3 = t3;
        } else {
            if (hist_idx >= 0) g_Hist[hist_idx] = histv;
        }
    }
    // Launch-exit state: g_cnt == 0, g_gen == base + SS - 1  (replay-safe).
}

// ---------------------------------------------------------------------------
// Output GEMM: out[b][s'][o] = Hist[s'][b][:] . Wl[o][:] + bl[o]  (fp32)
__global__ void __launch_bounds__(256, 2) output_gemm(
    const float* __restrict__ Wl, const float* __restrict__ bl,
    float* __restrict__ out)
{
    constexpr int BM = 128, BN = 128, BK = 8;
    __shared__ float As[BK][BM + 4];
    __shared__ float Bs[BK][BN + 4];

    const int bx = blockIdx.x;
    const int by = blockIdx.y;
    const int m0 = by * BM;
    const int n0g = bx * BN;

    const int tid  = threadIdx.x;
    const int arow = tid >> 1, acol = (tid & 1) * 4;
    const int brow = tid >> 1, bcol = (tid & 1) * 4;
    const int tx = tid & 15, ty = tid >> 4;

    const float* apk = g_Hist + (size_t)(m0 + arow) * HH + acol;
    const float* bpk = Wl + (size_t)(n0g + brow) * HH + bcol;

    unsigned long long acc2[8][4];
#pragma unroll
    for (int i = 0; i < 8; i++)
#pragma unroll
        for (int j = 0; j < 4; j++) acc2[i][j] = 0ULL;

    float4 av = *(const float4*)(apk);
    float4 bv = *(const float4*)(bpk);

    for (int k0 = 0; k0 < HH; k0 += BK) {
        As[acol + 0][arow] = av.x; As[acol + 1][arow] = av.y;
        As[acol + 2][arow] = av.z; As[acol + 3][arow] = av.w;
        Bs[bcol + 0][brow] = bv.x; Bs[bcol + 1][brow] = bv.y;
        Bs[bcol + 2][brow] = bv.z; Bs[bcol + 3][brow] = bv.w;
        __syncthreads();
        if (k0 + BK < HH) {
            av = *(const float4*)(apk + k0 + BK);
            bv = *(const float4*)(bpk + k0 + BK);
        }
#pragma unroll
        for (int k = 0; k < BK; k++) {
            float ra[8];
            *(float4*)(ra)     = *(const float4*)(&As[k][4 * ty]);
            *(float4*)(ra + 4) = *(const float4*)(&As[k][64 + 4 * ty]);
            const ulonglong2 b01 = *(const ulonglong2*)(&Bs[k][4 * tx]);
            const ulonglong2 b23 = *(const ulonglong2*)(&Bs[k][64 + 4 * tx]);
#pragma unroll
            for (int i = 0; i < 8; i++) {
                const unsigned long long a2 = splat2(ra[i]);
                ffma2(acc2[i][0], a2, b01.x);
                ffma2(acc2[i][1], a2, b01.y);
                ffma2(acc2[i][2], a2, b23.x);
                ffma2(acc2[i][3], a2, b23.y);
            }
        }
        __syncthreads();
    }

    float acc[8][8];
#pragma unroll
    for (int i = 0; i < 8; i++)
#pragma unroll
        for (int jp = 0; jp < 4; jp++) {
            float2 f = unpack2(acc2[i][jp]);
            acc[i][2 * jp] = f.x; acc[i][2 * jp + 1] = f.y;
        }

#pragma unroll
    for (int i = 0; i < 8; i++) {
        const int m = m0 + (i >> 2) * 64 + 4 * ty + (i & 3);
        const int sp = m >> 5, bB = m & 31;
#pragma unroll
        for (int jh = 0; jh < 2; jh++) {
            const int n = n0g + jh * 64 + 4 * tx;
            float4 v = make_float4(acc[i][jh * 4 + 0] + bl[n + 0],
                                   acc[i][jh * 4 + 1] + bl[n + 1],
                                   acc[i][jh * 4 + 2] + bl[n + 2],
                                   acc[i][jh * 4 + 3] + bl[n + 3]);
            *(float4*)(out + ((size_t)bB * (SS / 2) + sp) * II + n) = v;
        }
    }
}

// ---------------------------------------------------------------------------
extern "C" void kernel_launch(void* const* d_in, const int* in_sizes, int n_in,
                              void* d_out, int out_size)
{
    const float* x   = (const float*)d_in[0];
    const float* Wz  = (const float*)d_in[1];  const float* bz  = (const float*)d_in[2];
    const float* Wi  = (const float*)d_in[3];  const float* bi  = (const float*)d_in[4];
    const float* Wf  = (const float*)d_in[5];  const float* bf  = (const float*)d_in[6];
    const float* Wo  = (const float*)d_in[7];  const float* bo  = (const float*)d_in[8];
    const float* Rz  = (const float*)d_in[9];  const float* brz = (const float*)d_in[10];
    const float* Ri  = (const float*)d_in[11]; const float* bri = (const float*)d_in[12];
    const float* Rf  = (const float*)d_in[13]; const float* brf = (const float*)d_in[14];
    const float* Ro  = (const float*)d_in[15]; const float* bro = (const float*)d_in[16];
    const float* Wl  = (const float*)d_in[17]; const float* bl  = (const float*)d_in[18];
    float* out = (float*)d_out;

    // 0) Convert x/W/R to bf16 hi/lo
    convert_prepass<<<592, 256>>>(x, Wz, Wi, Wf, Wo, Rz, Ri, Rf, Ro);

    // 1) Tensor-core (HMMA) input projections -> g_G
    cudaFuncSetAttribute(input_gemm_tc, cudaFuncAttributeMaxDynamicSharedMemorySize, IG_SMEM);
    input_gemm_tc<<<dim3(16, 256), 256, IG_SMEM>>>(bz, bi, bf, bo);

    // 2) Hybrid tensor+fp32 persistent recurrence -> g_Hist
    cudaFuncSetAttribute(recurrence, cudaFuncAttributeMaxDynamicSharedMemorySize, RC_SMEM);
    recurrence<<<NB, NT, RC_SMEM>>>(Rz, Ri, Rf, Ro, brz, bri, brf, bro);

    // 3) Output projection -> d_out
    output_gemm<<<dim3(4, 128), 256>>>(Wl, bl, out);
}

// round 15
// speedup vs baseline: 1.0745x; 1.0745x over previous
#include <cuda_runtime.h>
#include <cuda_bf16.h>
#include <cstdint>
#include <cstddef>

// Problem dims (fixed by dataset)
#define BB 32
#define SS 1024
#define II 512
#define HH 512
#define NB 128        // persistent blocks in recurrence
#define NT 256        // threads per recurrence block (8 warps)

// ---------------------------------------------------------------------------
// Scratch (device globals: allocation-free per harness rules)
__device__ float g_G[(size_t)SS * 2048 * BB];          // [s][n][b]
__device__ float g_Hist[(size_t)(SS / 2) * BB * HH];   // [s'][b][h]
__device__ __nv_bfloat16 g_hbf[2][2][BB][HH];          // [buf][hi/lo][b][k]
__device__ unsigned g_cnt_grp[8 * 32];                 // spread group counters
__device__ unsigned g_cnt_root;
__device__ volatile unsigned g_gen;
// bf16 hi/lo operands for tensor-core GEMMs
__device__ __nv_bfloat16 g_xh[(size_t)SS * BB * II];   // [m=s*32+b][i]
__device__ __nv_bfloat16 g_xl[(size_t)SS * BB * II];
__device__ __nv_bfloat16 g_Wh[2048 * II];              // [n=g*512+h][i]
__device__ __nv_bfloat16 g_Wl[2048 * II];
__device__ __nv_bfloat16 g_Rh[2048 * HH];              // [n=g*512+h][k]
__device__ __nv_bfloat16 g_Rl[2048 * HH];

__device__ __forceinline__ float sigf(float x) { return 1.0f / (1.0f + expf(-x)); }

// Packed fp32x2 helpers (output GEMM)
__device__ __forceinline__ void ffma2(unsigned long long& d,
                                      unsigned long long a,
                                      unsigned long long b) {
    asm("fma.rn.f32x2 %0, %1, %2, %0;" : "+l"(d) : "l"(a), "l"(b));
}
__device__ __forceinline__ unsigned long long splat2(float x) {
    unsigned long long r;
    asm("mov.b64 %0, {%1, %1};" : "=l"(r) : "f"(x));
    return r;
}
__device__ __forceinline__ float2 unpack2(unsigned long long v) {
    float2 f;
    asm("mov.b64 {%0, %1}, %2;" : "=f"(f.x), "=f"(f.y) : "l"(v));
    return f;
}

// Base-ISA async-copy + HMMA + ldmatrix helpers (compute_100-safe)
__device__ __forceinline__ uint32_t smem_u32(const void* p) {
    uint32_t a;
    asm("{ .reg .u64 t; cvta.to.shared.u64 t, %1; cvt.u32.u64 %0, t; }"
        : "=r"(a) : "l"(p));
    return a;
}
__device__ __forceinline__ void cpa16(uint32_t dst, const void* src) {
    asm volatile("cp.async.cg.shared.global [%0], [%1], 16;"
                 :: "r"(dst), "l"(src) : "memory");
}
__device__ __forceinline__ void cpa_commit() {
    asm volatile("cp.async.commit_group;" ::: "memory");
}
__device__ __forceinline__ void cpa_wait0() {
    asm volatile("cp.async.wait_group 0;" ::: "memory");
}
__device__ __forceinline__ void mma_bf16(float* d, const uint32_t* a,
                                         const uint32_t* b) {
    asm volatile(
        "mma.sync.aligned.m16n8k16.row.col.f32.bf16.bf16.f32 "
        "{%0,%1,%2,%3}, {%4,%5,%6,%7}, {%8,%9}, {%0,%1,%2,%3};"
        : "+f"(d[0]), "+f"(d[1]), "+f"(d[2]), "+f"(d[3])
        : "r"(a[0]), "r"(a[1]), "r"(a[2]), "r"(a[3]), "r"(b[0]), "r"(b[1]));
}
__device__ __forceinline__ void ldsm4(uint32_t* r, uint32_t addr) {
    asm volatile("ldmatrix.sync.aligned.m8n8.x4.shared.b16 {%0,%1,%2,%3}, [%4];"
                 : "=r"(r[0]), "=r"(r[1]), "=r"(r[2]), "=r"(r[3]) : "r"(addr));
}

// ---------------------------------------------------------------------------
// Prepass: x -> g_xh/g_xl ([m][i]),  W -> g_Wh/g_Wl,  R -> g_Rh/g_Rl.
__global__ void __launch_bounds__(256) convert_prepass(
    const float* __restrict__ x,
    const float* __restrict__ Wz, const float* __restrict__ Wi,
    const float* __restrict__ Wf, const float* __restrict__ Wo,
    const float* __restrict__ Rz, const float* __restrict__ Ri,
    const float* __restrict__ Rf, const float* __restrict__ Ro)
{
    const int total = 4194304 + 262144 + 262144;   // float4 groups
    for (int t = blockIdx.x * blockDim.x + threadIdx.x; t < total;
         t += gridDim.x * blockDim.x) {
        float4 v;
        uint2* oh;
        uint2* ol;
        size_t oidx;
        if (t < 4194304) {                 // x part
            const int b = t >> 17, s = (t >> 7) & 1023, i4 = t & 127;
            v = ((const float4*)x)[(size_t)t];
            const int m = s * 32 + b;
            oidx = (size_t)m * 128 + i4;
            oh = (uint2*)g_xh; ol = (uint2*)g_xl;
        } else if (t < 4194304 + 262144) { // W part
            const int u = t - 4194304;
            const int n = u >> 7, i4 = u & 127;
            const int g = n >> 9, hr = n & 511;
            const float* Wg = (g == 0) ? Wz : (g == 1) ? Wi : (g == 2) ? Wf : Wo;
            v = ((const float4*)Wg)[(size_t)hr * 128 + i4];
            oidx = (size_t)n * 128 + i4;
            oh = (uint2*)g_Wh; ol = (uint2*)g_Wl;
        } else {                           // R part
            const int u = t - 4194304 - 262144;
            const int n = u >> 7, i4 = u & 127;
            const int g = n >> 9, hr = n & 511;
            const float* Rg = (g == 0) ? Rz : (g == 1) ? Ri : (g == 2) ? Rf : Ro;
            v = ((const float4*)Rg)[(size_t)hr * 128 + i4];
            oidx = (size_t)n * 128 + i4;
            oh = (uint2*)g_Rh; ol = (uint2*)g_Rl;
        }
        unsigned short h[4], l[4];
        const float* f = (const float*)&v;
#pragma unroll
        for (int j = 0; j < 4; j++) {
            __nv_bfloat16 bh = __float2bfloat16_rn(f[j]);
            float r = f[j] - __bfloat162float(bh);
            __nv_bfloat16 bl = __float2bfloat16_rn(r);
            h[j] = __bfloat16_as_ushort(bh);
            l[j] = __bfloat16_as_ushort(bl);
        }
        uint2 uh, ul;
        uh.x = (uint32_t)h[0] | ((uint32_t)h[1] << 16);
        uh.y = (uint32_t)h[2] | ((uint32_t)h[3] << 16);
        ul.x = (uint32_t)l[0] | ((uint32_t)l[1] << 16);
        ul.y = (uint32_t)l[2] | ((uint32_t)l[3] << 16);
        oh[oidx] = uh;
        ol[oidx] = ul;
    }
}

// ---------------------------------------------------------------------------
// Tensor-core input GEMM (HMMA, unchanged from R10 pass): G = X·W^T + bias.
#define IG_PITCH 72
#define IG_ARR   (128 * IG_PITCH)
#define IG_BUF   (4 * IG_ARR)
#define IG_SMEM  (2 * IG_BUF * 2)
__global__ void __launch_bounds__(256, 1) input_gemm_tc(
    const float* __restrict__ bz, const float* __restrict__ bi,
    const float* __restrict__ bf, const float* __restrict__ bo)
{
    extern __shared__ __nv_bfloat16 smb[];
    const uint32_t sb0 = smem_u32(smb);
    const int tid = threadIdx.x;
    const int wid = tid >> 5, lane = tid & 31;
    const int g = lane >> 2, t = lane & 3;
    const int wm = wid >> 2, wn = wid & 3;
    const int bx = blockIdx.x, by = blockIdx.y;
    const int n0 = bx * 128, m0 = by * 128;

    auto stage = [&](int c, int buf) {
        const uint32_t base = sb0 + (uint32_t)buf * (IG_BUF * 2);
        const uint4* srcA_h = (const uint4*)g_xh + (size_t)m0 * 64 + c * 8;
        const uint4* srcA_l = (const uint4*)g_xl + (size_t)m0 * 64 + c * 8;
        const uint4* srcB_h = (const uint4*)g_Wh + (size_t)n0 * 64 + c * 8;
        const uint4* srcB_l = (const uint4*)g_Wl + (size_t)n0 * 64 + c * 8;
        const uint4* srcs[4] = { srcA_h, srcA_l, srcB_h, srcB_l };
#pragma unroll
        for (int a = 0; a < 4; a++) {
#pragma unroll
            for (int i = 0; i < 4; i++) {
                const int idx = i * 256 + tid;
                const int r = idx >> 3, u = idx & 7;
                cpa16(base + (uint32_t)(a * (IG_ARR * 2) + r * (IG_PITCH * 2) + u * 16),
                      srcs[a] + (size_t)r * 64 + u);
            }
        }
        cpa_commit();
    };

    float acc[4][4][4];
#pragma unroll
    for (int mi = 0; mi < 4; mi++)
#pragma unroll
        for (int ni = 0; ni < 4; ni++)
#pragma unroll
            for (int r = 0; r < 4; r++) acc[mi][ni][r] = 0.0f;

    stage(0, 0);

    for (int c = 0; c < 8; c++) {
        cpa_wait0();
        __syncthreads();
        if (c + 1 < 8) stage(c + 1, (c + 1) & 1);

        const __nv_bfloat16* Ah = smb + (size_t)(c & 1) * IG_BUF;
        const __nv_bfloat16* Al = Ah + IG_ARR;
        const __nv_bfloat16* Bh = Ah + 2 * IG_ARR;
        const __nv_bfloat16* Bl = Ah + 3 * IG_ARR;

#pragma unroll
        for (int ks = 0; ks < 4; ks++) {
            const int k0 = ks * 16;
            uint32_t ah[4][4], al[4][4], bh[4][2], bl[4][2];
#pragma unroll
            for (int mi = 0; mi < 4; mi++) {
                const int r0 = wm * 64 + mi * 16 + g;
                const int cA = k0 + 2 * t;
                ah[mi][0] = *(const uint32_t*)(Ah + r0 * IG_PITCH + cA);
                ah[mi][1] = *(const uint32_t*)(Ah + (r0 + 8) * IG_PITCH + cA);
                ah[mi][2] = *(const uint32_t*)(Ah + r0 * IG_PITCH + cA + 8);
                ah[mi][3] = *(const uint32_t*)(Ah + (r0 + 8) * IG_PITCH + cA + 8);
                al[mi][0] = *(const uint32_t*)(Al + r0 * IG_PITCH + cA);
                al[mi][1] = *(const uint32_t*)(Al + (r0 + 8) * IG_PITCH + cA);
                al[mi][2] = *(const uint32_t*)(Al + r0 * IG_PITCH + cA + 8);
                al[mi][3] = *(const uint32_t*)(Al + (r0 + 8) * IG_PITCH + cA + 8);
            }
#pragma unroll
            for (int ni = 0; ni < 4; ni++) {
                const int rB = wn * 32 + ni * 8 + g;
                const int cB = k0 + 2 * t;
                bh[ni][0] = *(const uint32_t*)(Bh + rB * IG_PITCH + cB);
                bh[ni][1] = *(const uint32_t*)(Bh + rB * IG_PITCH + cB + 8);
                bl[ni][0] = *(const uint32_t*)(Bl + rB * IG_PITCH + cB);
                bl[ni][1] = *(const uint32_t*)(Bl + rB * IG_PITCH + cB + 8);
            }
#pragma unroll
            for (int mi = 0; mi < 4; mi++)
#pragma unroll
                for (int ni = 0; ni < 4; ni++) {
                    mma_bf16(acc[mi][ni], ah[mi], bh[ni]);
                    mma_bf16(acc[mi][ni], ah[mi], bl[ni]);
                    mma_bf16(acc[mi][ni], al[mi], bh[ni]);
                }
        }
        __syncthreads();
    }

    const int gate = bx >> 2;
    const float* bias = (gate == 0) ? bz : (gate == 1) ? bi : (gate == 2) ? bf : bo;
    const int nlb = (bx & 3) * 128;
#pragma unroll
    for (int mi = 0; mi < 4; mi++) {
        const int row0 = m0 + wm * 64 + mi * 16 + g;
        const int row1 = row0 + 8;
        const int s0 = row0 >> 5, b0 = row0 & 31;
        const int s1 = row1 >> 5, b1 = row1 & 31;
#pragma unroll
        for (int ni = 0; ni < 4; ni++) {
            const int nl = wn * 32 + ni * 8 + 2 * t;
            const int n = n0 + nl;
            const float bv0 = bias[nlb + nl], bv1 = bias[nlb + nl + 1];
            g_G[((size_t)s0 * 2048 + n) * BB + b0]     = acc[mi][ni][0] + bv0;
            g_G[((size_t)s0 * 2048 + n + 1) * BB + b0] = acc[mi][ni][1] + bv1;
            g_G[((size_t)s1 * 2048 + n) * BB + b1]     = acc[mi][ni][2] + bv0;
            g_G[((size_t)s1 * 2048 + n + 1) * BB + b1] = acc[mi][ni][3] + bv1;
        }
    }
}

// ---------------------------------------------------------------------------
// Tensor-core persistent recurrence (R10-exact structure). 128 blocks x 256
// threads, 1 block/SM.  Block = (hcols jc=(bid>>1)*8, b-half b0g=(bid&1)*16).
// 8 warps k-split x64, bf16 hi/lo mma (3 passes), cp.async h staging,
// smem reduce, gate on tid<128.  ONLY change vs R10: two-level tree barrier.
// smem (bf16 elems): Rs hi 0, lo 16640; hs hi 33280, lo 41600; total 49920.
#define RS_H 0
#define RS_L 16640
#define HS_H 33280
#define HS_L 41600
#define RC_PITCH 520
#define RC_SMEM (49920 * 2 + (4608 + 128 + 32) * 4)   // 118,912 B
__global__ void __launch_bounds__(NT, 1) recurrence(
    const float* __restrict__ brz, const float* __restrict__ bri,
    const float* __restrict__ brf, const float* __restrict__ bro)
{
    extern __shared__ __nv_bfloat16 smb[];
    float* red = (float*)(smb + 49920);   // [8][32][18] partials
    float* csm = red + 4608;              // 128 cell states
    float* brs = csm + 128;               // 32 biases (p = g*8+c)
    const uint32_t sbb = smem_u32(smb);

    const int tid = threadIdx.x;
    const int bid = blockIdx.x;
    const int jc  = (bid >> 1) * 8;
    const int b0g = (bid & 1) * 16;
    const int w = tid >> 5, lane = tid & 31;

    __shared__ unsigned s_base;
    if (tid == 0) s_base = g_gen;     // consistent snapshot (see R1 notes)

    // Stage R (32 rows m=g*8+c -> global n=g*512+jc+c), hi+lo, pitch 520.
    for (int i = 0; i < 16; i++) {
        const int idx = i * 256 + tid;            // 4096 uint4 total
        const int part = idx >> 11, rest = idx & 2047;
        const int m = rest >> 6, u = rest & 63;
        const int n = (m >> 3) * 512 + jc + (m & 7);
        const uint4 v = *((const uint4*)(part ? g_Rl : g_Rh) + (size_t)n * 64 + u);
        *(uint4*)(smb + (part ? RS_L : RS_H) + m * RC_PITCH + u * 8) = v;
    }
    if (tid < 32) {
        const int g = tid >> 3, c = tid & 7;
        const float* bg = (g == 0) ? brz : (g == 1) ? bri : (g == 2) ? brf : bro;
        brs[tid] = bg[jc + c];
    }
    if (tid < 128) csm[tid] = 0.0f;
    __syncthreads();
    const unsigned base = s_base;

    // ldmatrix lane-address components
    const int arow = (lane & 15) * RC_PITCH;
    const int akad = (lane >> 4) << 3;
    const int brow = (((lane >> 4) & 1) * 8 + (lane & 7)) * RC_PITCH;
    const int bkad = ((lane >> 3) & 1) * 8;
    // cell roles (threads 0..127)
    const int c_ = (tid >> 4) & 7;    // hcol 0..7
    const int b_ = tid & 15;          // batch 0..15
    const int grp = lane >> 2, qp = lane & 3;

    // G prefetch for s = 0 (threads 0..127)
    float gv0 = 0.f, gv1 = 0.f, gv2 = 0.f, gv3 = 0.f;
    if (tid < 128) {
        gv0 = g_G[(0 * 512 + jc + c_) * BB + b0g + b_];
        gv1 = g_G[(1 * 512 + jc + c_) * BB + b0g + b_];
        gv2 = g_G[(2 * 512 + jc + c_) * BB + b0g + b_];
        gv3 = g_G[(3 * 512 + jc + c_) * BB + b0g + b_];
    }

    float histv = 0.0f;
    int   hist_idx = -1;

    for (int s = 0; s < SS; ++s) {
        // Stage h (bf16 hi/lo, 16 b-rows x 512 k, pitch 520) via cp.async.
        if (s == 0) {
            const uint4 z4 = make_uint4(0, 0, 0, 0);
#pragma unroll
            for (int i = 0; i < 8; i++) {
                const int idx = i * 256 + tid;        // 2048 uint4
                const int part = idx >> 10, rest = idx & 1023;
                const int r = rest >> 6, u = rest & 63;
                *(uint4*)(smb + (part ? HS_L : HS_H) + r * RC_PITCH + u * 8) = z4;
            }
        } else {
            const int pb = (s - 1) & 1;
            const uint4* hsrc = (const uint4*)g_hbf;
#pragma unroll
            for (int i = 0; i < 8; i++) {
                const int idx = i * 256 + tid;
                const int part = idx >> 10, rest = idx & 1023;
                const int r = rest >> 6, u = rest & 63;
                cpa16(sbb + 2 * (uint32_t)((part ? HS_L : HS_H) + r * RC_PITCH + u * 8),
                      hsrc + ((size_t)((pb * 2 + part) * 32 + b0g + r)) * 64 + u);
            }
            cpa_commit();
            cpa_wait0();
        }
        __syncthreads();

        // MMA: warp w covers k in [w*64, w*64+64), 4 k-steps of 16.
        float acc[2][2][4];
#pragma unroll
        for (int mi = 0; mi < 2; mi++)
#pragma unroll
            for (int ni = 0; ni < 2; ni++)
#pragma unroll
                for (int r = 0; r < 4; r++) acc[mi][ni][r] = 0.0f;

#pragma unroll
        for (int ks = 0; ks < 4; ks++) {
            const int kb = w * 64 + ks * 16;
            uint32_t Ah0[4], Ah1[4], Al0[4], Al1[4], Bh[4], Bl[4];
            ldsm4(Ah0, sbb + 2 * (RS_H + arow + kb + akad));
            ldsm4(Ah1, sbb + 2 * (RS_H + 16 * RC_PITCH + arow + kb + akad));
            ldsm4(Al0, sbb + 2 * (RS_L + arow + kb + akad));
            ldsm4(Al1, sbb + 2 * (RS_L + 16 * RC_PITCH + arow + kb + akad));
            ldsm4(Bh,  sbb + 2 * (HS_H + brow + kb + bkad));
            ldsm4(Bl,  sbb + 2 * (HS_L + brow + kb + bkad));
            mma_bf16(acc[0][0], Ah0, Bh);     mma_bf16(acc[0][1], Ah0, Bh + 2);
            mma_bf16(acc[1][0], Ah1, Bh);     mma_bf16(acc[1][1], Ah1, Bh + 2);
            mma_bf16(acc[0][0], Ah0, Bl);     mma_bf16(acc[0][1], Ah0, Bl + 2);
            mma_bf16(acc[1][0], Ah1, Bl);     mma_bf16(acc[1][1], Ah1, Bl + 2);
            mma_bf16(acc[0][0], Al0, Bh);     mma_bf16(acc[0][1], Al0, Bh + 2);
            mma_bf16(acc[1][0], Al1, Bh);     mma_bf16(acc[1][1], Al1, Bh + 2);
        }

        // Partials -> red[w][n=0..31][b=0..15] pitch 18
#pragma unroll
        for (int mi = 0; mi < 2; mi++)
#pragma unroll
            for (int ni = 0; ni < 2; ni++) {
                const int row = mi * 16 + grp;
                const int col = ni * 8 + qp * 2;
                *(float2*)&red[(w * 32 + row) * 18 + col] =
                    make_float2(acc[mi][ni][0], acc[mi][ni][1]);
                *(float2*)&red[(w * 32 + row + 8) * 18 + col] =
                    make_float2(acc[mi][ni][2], acc[mi][ni][3]);
            }
        __syncthreads();

        // Gate phase (threads 0..127): cell (hcol c_, batch b_).
        if (tid < 128) {
            float pz = gv0 + brs[0 + c_];
            float pi_ = gv1 + brs[8 + c_];
            float pf = gv2 + brs[16 + c_];
            float po = gv3 + brs[24 + c_];
#pragma unroll
            for (int q = 0; q < 8; q++) {
                pz  += red[(q * 32 + 0 + c_) * 18 + b_];
                pi_ += red[(q * 32 + 8 + c_) * 18 + b_];
                pf  += red[(q * 32 + 16 + c_) * 18 + b_];
                po  += red[(q * 32 + 24 + c_) * 18 + b_];
            }
            const float z  = tanhf(pz);
            const float iv = sigf(pi_);
            const float f  = sigf(pf);
            const float o  = sigf(po);
            const float cc = fmaf(f, csm[tid], z * iv);
            csm[tid] = cc;
            const float h = o * tanhf(cc);
            // Emit h as bf16 hi/lo to [buf][part][b][k]
            const __nv_bfloat16 hh = __float2bfloat16_rn(h);
            const __nv_bfloat16 hl = __float2bfloat16_rn(h - __bfloat162float(hh));
            g_hbf[s & 1][0][b0g + b_][jc + c_] = hh;
            g_hbf[s & 1][1][b0g + b_][jc + c_] = hl;
            histv = h;
            hist_idx = (s >= SS / 2)
                     ? (int)(((size_t)(s - SS / 2) * BB + b0g + b_) * HH + jc + c_)
                     : -1;
        }

        // Prefetch next step's G, two-level grid barrier, deferred Hist store.
        if (s < SS - 1) {
            float t0 = 0.f, t1 = 0.f, t2 = 0.f, t3 = 0.f;
            if (tid < 128) {
                const float* Gn = g_G + (size_t)(s + 1) * (2048 * BB);
                t0 = Gn[(0 * 512 + jc + c_) * BB + b0g + b_];
                t1 = Gn[(1 * 512 + jc + c_) * BB + b0g + b_];
                t2 = Gn[(2 * 512 + jc + c_) * BB + b0g + b_];
                t3 = Gn[(3 * 512 + jc + c_) * BB + b0g + b_];
            }
            __threadfence();
            __syncthreads();
            if (tid == 0) {
                const unsigned tgt = base + (unsigned)s + 1u;
                bool released = false;
                // Level 1: 8 spread group counters (16 arrivals each).
                if (atomicAdd(&g_cnt_grp[(bid >> 4) << 5], 1u) == 15u) {
                    // Level 2: 8 group-leaders race on the root.
                    if (atomicAdd(&g_cnt_root, 1u) == 7u) {
                        // All 128 blocks arrived; everyone else spins on
                        // g_gen and cannot touch counters -> reset is safe.
                        atomicExch(&g_cnt_root, 0u);
#pragma unroll
                        for (int q = 0; q < 8; q++)
                            atomicExch(&g_cnt_grp[q << 5], 0u);
                        __threadfence();
                        g_gen = tgt;
                        released = true;
                    }
                }
                if (!released) {
                    while ((int)(g_gen - tgt) < 0) __nanosleep(32);
                    __threadfence();
                }
            }
            __syncthreads();
            if (hist_idx >= 0) g_Hist[hist_idx] = histv;
            gv0 = t0; gv1 = t1; gv2 = t2; gv3 = t3;
        } else {
            if (hist_idx >= 0) g_Hist[hist_idx] = histv;
        }
    }
    // Exit state: all counters 0, g_gen == base + SS - 1  (replay-safe).
}

// ---------------------------------------------------------------------------
// Output GEMM: out[b][s'][o] = Hist[s'][b][:] . Wl[o][:] + bl[o]  (fp32)
__global__ void __launch_bounds__(256, 2) output_gemm(
    const float* __restrict__ Wl, const float* __restrict__ bl,
    float* __restrict__ out)
{
    constexpr int BM = 128, BN = 128, BK = 8;
    __shared__ float As[BK][BM + 4];
    __shared__ float Bs[BK][BN + 4];

    const int bx = blockIdx.x;
    const int by = blockIdx.y;
    const int m0 = by * BM;
    const int n0g = bx * BN;

    const int tid  = threadIdx.x;
    const int arow = tid >> 1, acol = (tid & 1) * 4;
    const int brow = tid >> 1, bcol = (tid & 1) * 4;
    const int tx = tid & 15, ty = tid >> 4;

    const float* apk = g_Hist + (size_t)(m0 + arow) * HH + acol;
    const float* bpk = Wl + (size_t)(n0g + brow) * HH + bcol;

    unsigned long long acc2[8][4];
#pragma unroll
    for (int i = 0; i < 8; i++)
#pragma unroll
        for (int j = 0; j < 4; j++) acc2[i][j] = 0ULL;

    float4 av = *(const float4*)(apk);
    float4 bv = *(const float4*)(bpk);

    for (int k0 = 0; k0 < HH; k0 += BK) {
        As[acol + 0][arow] = av.x; As[acol + 1][arow] = av.y;
        As[acol + 2][arow] = av.z; As[acol + 3][arow] = av.w;
        Bs[bcol + 0][brow] = bv.x; Bs[bcol + 1][brow] = bv.y;
        Bs[bcol + 2][brow] = bv.z; Bs[bcol + 3][brow] = bv.w;
        __syncthreads();
        if (k0 + BK < HH) {
            av = *(const float4*)(apk + k0 + BK);
            bv = *(const float4*)(bpk + k0 + BK);
        }
#pragma unroll
        for (int k = 0; k < BK; k++) {
            float ra[8];
            *(float4*)(ra)     = *(const float4*)(&As[k][4 * ty]);
            *(float4*)(ra + 4) = *(const float4*)(&As[k][64 + 4 * ty]);
            const ulonglong2 b01 = *(const ulonglong2*)(&Bs[k][4 * tx]);
            const ulonglong2 b23 = *(const ulonglong2*)(&Bs[k][64 + 4 * tx]);
#pragma unroll
            for (int i = 0; i < 8; i++) {
                const unsigned long long a2 = splat2(ra[i]);
                ffma2(acc2[i][0], a2, b01.x);
                ffma2(acc2[i][1], a2, b01.y);
                ffma2(acc2[i][2], a2, b23.x);
                ffma2(acc2[i][3], a2, b23.y);
            }
        }
        __syncthreads();
    }

    float acc[8][8];
#pragma unroll
    for (int i = 0; i < 8; i++)
#pragma unroll
        for (int jp = 0; jp < 4; jp++) {
            float2 f = unpack2(acc2[i][jp]);
            acc[i][2 * jp] = f.x; acc[i][2 * jp + 1] = f.y;
        }

#pragma unroll
    for (int i = 0; i < 8; i++) {
        const int m = m0 + (i >> 2) * 64 + 4 * ty + (i & 3);
        const int sp = m >> 5, bB = m & 31;
#pragma unroll
        for (int jh = 0; jh < 2; jh++) {
            const int n = n0g + jh * 64 + 4 * tx;
            float4 v = make_float4(acc[i][jh * 4 + 0] + bl[n + 0],
                                   acc[i][jh * 4 + 1] + bl[n + 1],
                                   acc[i][jh * 4 + 2] + bl[n + 2],
                                   acc[i][jh * 4 + 3] + bl[n + 3]);
            *(float4*)(out + ((size_t)bB * (SS / 2) + sp) * II + n) = v;
        }
    }
}

// ---------------------------------------------------------------------------
extern "C" void kernel_launch(void* const* d_in, const int* in_sizes, int n_in,
                              void* d_out, int out_size)
{
    const float* x   = (const float*)d_in[0];
    const float* Wz  = (const float*)d_in[1];  const float* bz  = (const float*)d_in[2];
    const float* Wi  = (const float*)d_in[3];  const float* bi  = (const float*)d_in[4];
    const float* Wf  = (const float*)d_in[5];  const float* bf  = (const float*)d_in[6];
    const float* Wo  = (const float*)d_in[7];  const float* bo  = (const float*)d_in[8];
    const float* Rz  = (const float*)d_in[9];  const float* brz = (const float*)d_in[10];
    const float* Ri  = (const float*)d_in[11]; const float* bri = (const float*)d_in[12];
    const float* Rf  = (const float*)d_in[13]; const float* brf = (const float*)d_in[14];
    const float* Ro  = (const float*)d_in[15]; const float* bro = (const float*)d_in[16];
    const float* Wl  = (const float*)d_in[17]; const float* bl  = (const float*)d_in[18];
    float* out = (float*)d_out;

    // 0) Convert x/W/R to bf16 hi/lo
    convert_prepass<<<592, 256>>>(x, Wz, Wi, Wf, Wo, Rz, Ri, Rf, Ro);

    // 1) Tensor-core (HMMA) input projections -> g_G
    cudaFuncSetAttribute(input_gemm_tc, cudaFuncAttributeMaxDynamicSharedMemorySize, IG_SMEM);
    input_gemm_tc<<<dim3(16, 256), 256, IG_SMEM>>>(bz, bi, bf, bo);

    // 2) Tensor-core persistent recurrence -> g_Hist
    cudaFuncSetAttribute(recurrence, cudaFuncAttributeMaxDynamicSharedMemorySize, RC_SMEM);
    recurrence<<<NB, NT, RC_SMEM>>>(brz, bri, brf, bro);

    // 3) Output projection -> d_out
    output_gemm<<<dim3(4, 128), 256>>>(Wl, bl, out);
}

// round 17
// speedup vs baseline: 1.2169x; 1.1325x over previous
#include <cuda_runtime.h>
#include <cuda_bf16.h>
#include <cstdint>
#include <cstddef>

// Problem dims (fixed by dataset)
#define BB 32
#define SS 1024
#define II 512
#define HH 512
#define NB 128        // persistent blocks in recurrence
#define NT 256        // threads per recurrence block (8 warps)

// ---------------------------------------------------------------------------
// Scratch (device globals: allocation-free per harness rules)
__device__ float g_G[(size_t)SS * 2048 * BB];          // [s][n][b]
__device__ float g_Hist[(size_t)(SS / 2) * BB * HH];   // [s'][b][h]
__device__ __nv_bfloat16 g_hbf[2][2][BB][HH];          // [buf][hi/lo][b][k]
__device__ unsigned g_cnt2[64];                        // two half-barriers, 128B apart
__device__ volatile unsigned g_gen2[64];
// bf16 hi/lo operands for tensor-core GEMMs
__device__ __nv_bfloat16 g_xh[(size_t)SS * BB * II];   // [m=s*32+b][i]
__device__ __nv_bfloat16 g_xl[(size_t)SS * BB * II];
__device__ __nv_bfloat16 g_Wh[2048 * II];              // [n=g*512+h][i]
__device__ __nv_bfloat16 g_Wl[2048 * II];
__device__ __nv_bfloat16 g_Rh[2048 * HH];              // [n=g*512+h][k]
__device__ __nv_bfloat16 g_Rl[2048 * HH];

__device__ __forceinline__ float sigf(float x) { return 1.0f / (1.0f + expf(-x)); }

// Packed fp32x2 helpers (output GEMM)
__device__ __forceinline__ void ffma2(unsigned long long& d,
                                      unsigned long long a,
                                      unsigned long long b) {
    asm("fma.rn.f32x2 %0, %1, %2, %0;" : "+l"(d) : "l"(a), "l"(b));
}
__device__ __forceinline__ unsigned long long splat2(float x) {
    unsigned long long r;
    asm("mov.b64 %0, {%1, %1};" : "=l"(r) : "f"(x));
    return r;
}
__device__ __forceinline__ float2 unpack2(unsigned long long v) {
    float2 f;
    asm("mov.b64 {%0, %1}, %2;" : "=f"(f.x), "=f"(f.y) : "l"(v));
    return f;
}

// Base-ISA async-copy + HMMA + ldmatrix helpers (compute_100-safe)
__device__ __forceinline__ uint32_t smem_u32(const void* p) {
    uint32_t a;
    asm("{ .reg .u64 t; cvta.to.shared.u64 t, %1; cvt.u32.u64 %0, t; }"
        : "=r"(a) : "l"(p));
    return a;
}
__device__ __forceinline__ void cpa16(uint32_t dst, const void* src) {
    asm volatile("cp.async.cg.shared.global [%0], [%1], 16;"
                 :: "r"(dst), "l"(src) : "memory");
}
__device__ __forceinline__ void cpa_commit() {
    asm volatile("cp.async.commit_group;" ::: "memory");
}
__device__ __forceinline__ void cpa_wait0() {
    asm volatile("cp.async.wait_group 0;" ::: "memory");
}
__device__ __forceinline__ void mma_bf16(float* d, const uint32_t* a,
                                         const uint32_t* b) {
    asm volatile(
        "mma.sync.aligned.m16n8k16.row.col.f32.bf16.bf16.f32 "
        "{%0,%1,%2,%3}, {%4,%5,%6,%7}, {%8,%9}, {%0,%1,%2,%3};"
        : "+f"(d[0]), "+f"(d[1]), "+f"(d[2]), "+f"(d[3])
        : "r"(a[0]), "r"(a[1]), "r"(a[2]), "r"(a[3]), "r"(b[0]), "r"(b[1]));
}
__device__ __forceinline__ void ldsm4(uint32_t* r, uint32_t addr) {
    asm volatile("ldmatrix.sync.aligned.m8n8.x4.shared.b16 {%0,%1,%2,%3}, [%4];"
                 : "=r"(r[0]), "=r"(r[1]), "=r"(r[2]), "=r"(r[3]) : "r"(addr));
}

// ---------------------------------------------------------------------------
// Prepass: x -> g_xh/g_xl ([m][i]),  W -> g_Wh/g_Wl,  R -> g_Rh/g_Rl.
__global__ void __launch_bounds__(256) convert_prepass(
    const float* __restrict__ x,
    const float* __restrict__ Wz, const float* __restrict__ Wi,
    const float* __restrict__ Wf, const float* __restrict__ Wo,
    const float* __restrict__ Rz, const float* __restrict__ Ri,
    const float* __restrict__ Rf, const float* __restrict__ Ro)
{
    const int total = 4194304 + 262144 + 262144;   // float4 groups
    for (int t = blockIdx.x * blockDim.x + threadIdx.x; t < total;
         t += gridDim.x * blockDim.x) {
        float4 v;
        uint2* oh;
        uint2* ol;
        size_t oidx;
        if (t < 4194304) {                 // x part
            const int b = t >> 17, s = (t >> 7) & 1023, i4 = t & 127;
            v = ((const float4*)x)[(size_t)t];
            const int m = s * 32 + b;
            oidx = (size_t)m * 128 + i4;
            oh = (uint2*)g_xh; ol = (uint2*)g_xl;
        } else if (t < 4194304 + 262144) { // W part
            const int u = t - 4194304;
            const int n = u >> 7, i4 = u & 127;
            const int g = n >> 9, hr = n & 511;
            const float* Wg = (g == 0) ? Wz : (g == 1) ? Wi : (g == 2) ? Wf : Wo;
            v = ((const float4*)Wg)[(size_t)hr * 128 + i4];
            oidx = (size_t)n * 128 + i4;
            oh = (uint2*)g_Wh; ol = (uint2*)g_Wl;
        } else {                           // R part
            const int u = t - 4194304 - 262144;
            const int n = u >> 7, i4 = u & 127;
            const int g = n >> 9, hr = n & 511;
            const float* Rg = (g == 0) ? Rz : (g == 1) ? Ri : (g == 2) ? Rf : Ro;
            v = ((const float4*)Rg)[(size_t)hr * 128 + i4];
            oidx = (size_t)n * 128 + i4;
            oh = (uint2*)g_Rh; ol = (uint2*)g_Rl;
        }
        unsigned short h[4], l[4];
        const float* f = (const float*)&v;
#pragma unroll
        for (int j = 0; j < 4; j++) {
            __nv_bfloat16 bh = __float2bfloat16_rn(f[j]);
            float r = f[j] - __bfloat162float(bh);
            __nv_bfloat16 bl = __float2bfloat16_rn(r);
            h[j] = __bfloat16_as_ushort(bh);
            l[j] = __bfloat16_as_ushort(bl);
        }
        uint2 uh, ul;
        uh.x = (uint32_t)h[0] | ((uint32_t)h[1] << 16);
        uh.y = (uint32_t)h[2] | ((uint32_t)h[3] << 16);
        ul.x = (uint32_t)l[0] | ((uint32_t)l[1] << 16);
        ul.y = (uint32_t)l[2] | ((uint32_t)l[3] << 16);
        oh[oidx] = uh;
        ol[oidx] = ul;
    }
}

// ---------------------------------------------------------------------------
// Tensor-core input GEMM (HMMA, unchanged from R10 pass): G = X·W^T + bias.
#define IG_PITCH 72
#define IG_ARR   (128 * IG_PITCH)
#define IG_BUF   (4 * IG_ARR)
#define IG_SMEM  (2 * IG_BUF * 2)
__global__ void __launch_bounds__(256, 1) input_gemm_tc(
    const float* __restrict__ bz, const float* __restrict__ bi,
    const float* __restrict__ bf, const float* __restrict__ bo)
{
    extern __shared__ __nv_bfloat16 smb[];
    const uint32_t sb0 = smem_u32(smb);
    const int tid = threadIdx.x;
    const int wid = tid >> 5, lane = tid & 31;
    const int g = lane >> 2, t = lane & 3;
    const int wm = wid >> 2, wn = wid & 3;
    const int bx = blockIdx.x, by = blockIdx.y;
    const int n0 = bx * 128, m0 = by * 128;

    auto stage = [&](int c, int buf) {
        const uint32_t base = sb0 + (uint32_t)buf * (IG_BUF * 2);
        const uint4* srcA_h = (const uint4*)g_xh + (size_t)m0 * 64 + c * 8;
        const uint4* srcA_l = (const uint4*)g_xl + (size_t)m0 * 64 + c * 8;
        const uint4* srcB_h = (const uint4*)g_Wh + (size_t)n0 * 64 + c * 8;
        const uint4* srcB_l = (const uint4*)g_Wl + (size_t)n0 * 64 + c * 8;
        const uint4* srcs[4] = { srcA_h, srcA_l, srcB_h, srcB_l };
#pragma unroll
        for (int a = 0; a < 4; a++) {
#pragma unroll
            for (int i = 0; i < 4; i++) {
                const int idx = i * 256 + tid;
                const int r = idx >> 3, u = idx & 7;
                cpa16(base + (uint32_t)(a * (IG_ARR * 2) + r * (IG_PITCH * 2) + u * 16),
                      srcs[a] + (size_t)r * 64 + u);
            }
        }
        cpa_commit();
    };

    float acc[4][4][4];
#pragma unroll
    for (int mi = 0; mi < 4; mi++)
#pragma unroll
        for (int ni = 0; ni < 4; ni++)
#pragma unroll
            for (int r = 0; r < 4; r++) acc[mi][ni][r] = 0.0f;

    stage(0, 0);

    for (int c = 0; c < 8; c++) {
        cpa_wait0();
        __syncthreads();
        if (c + 1 < 8) stage(c + 1, (c + 1) & 1);

        const __nv_bfloat16* Ah = smb + (size_t)(c & 1) * IG_BUF;
        const __nv_bfloat16* Al = Ah + IG_ARR;
        const __nv_bfloat16* Bh = Ah + 2 * IG_ARR;
        const __nv_bfloat16* Bl = Ah + 3 * IG_ARR;

#pragma unroll
        for (int ks = 0; ks < 4; ks++) {
            const int k0 = ks * 16;
            uint32_t ah[4][4], al[4][4], bh[4][2], bl[4][2];
#pragma unroll
            for (int mi = 0; mi < 4; mi++) {
                const int r0 = wm * 64 + mi * 16 + g;
                const int cA = k0 + 2 * t;
                ah[mi][0] = *(const uint32_t*)(Ah + r0 * IG_PITCH + cA);
                ah[mi][1] = *(const uint32_t*)(Ah + (r0 + 8) * IG_PITCH + cA);
                ah[mi][2] = *(const uint32_t*)(Ah + r0 * IG_PITCH + cA + 8);
                ah[mi][3] = *(const uint32_t*)(Ah + (r0 + 8) * IG_PITCH + cA + 8);
                al[mi][0] = *(const uint32_t*)(Al + r0 * IG_PITCH + cA);
                al[mi][1] = *(const uint32_t*)(Al + (r0 + 8) * IG_PITCH + cA);
                al[mi][2] = *(const uint32_t*)(Al + r0 * IG_PITCH + cA + 8);
                al[mi][3] = *(const uint32_t*)(Al + (r0 + 8) * IG_PITCH + cA + 8);
            }
#pragma unroll
            for (int ni = 0; ni < 4; ni++) {
                const int rB = wn * 32 + ni * 8 + g;
                const int cB = k0 + 2 * t;
                bh[ni][0] = *(const uint32_t*)(Bh + rB * IG_PITCH + cB);
                bh[ni][1] = *(const uint32_t*)(Bh + rB * IG_PITCH + cB + 8);
                bl[ni][0] = *(const uint32_t*)(Bl + rB * IG_PITCH + cB);
                bl[ni][1] = *(const uint32_t*)(Bl + rB * IG_PITCH + cB + 8);
            }
#pragma unroll
            for (int mi = 0; mi < 4; mi++)
#pragma unroll
                for (int ni = 0; ni < 4; ni++) {
                    mma_bf16(acc[mi][ni], ah[mi], bh[ni]);
                    mma_bf16(acc[mi][ni], ah[mi], bl[ni]);
                    mma_bf16(acc[mi][ni], al[mi], bh[ni]);
                }
        }
        __syncthreads();
    }

    const int gate = bx >> 2;
    const float* bias = (gate == 0) ? bz : (gate == 1) ? bi : (gate == 2) ? bf : bo;
    const int nlb = (bx & 3) * 128;
#pragma unroll
    for (int mi = 0; mi < 4; mi++) {
        const int row0 = m0 + wm * 64 + mi * 16 + g;
        const int row1 = row0 + 8;
        const int s0 = row0 >> 5, b0 = row0 & 31;
        const int s1 = row1 >> 5, b1 = row1 & 31;
#pragma unroll
        for (int ni = 0; ni < 4; ni++) {
            const int nl = wn * 32 + ni * 8 + 2 * t;
            const int n = n0 + nl;
            const float bv0 = bias[nlb + nl], bv1 = bias[nlb + nl + 1];
            g_G[((size_t)s0 * 2048 + n) * BB + b0]     = acc[mi][ni][0] + bv0;
            g_G[((size_t)s0 * 2048 + n + 1) * BB + b0] = acc[mi][ni][1] + bv1;
            g_G[((size_t)s1 * 2048 + n) * BB + b1]     = acc[mi][ni][2] + bv0;
            g_G[((size_t)s1 * 2048 + n + 1) * BB + b1] = acc[mi][ni][3] + bv1;
        }
    }
}

// ---------------------------------------------------------------------------
// Tensor-core persistent recurrence. 128 blocks x 256 threads, 1 block/SM.
// Block = (hcols jc=(bid>>1)*8, b-half b0g=(bid&1)*16).  Changes vs R10:
//  * A(R) ldmatrix fragments hoisted out of the step loop (register-resident)
//  * grid barrier split into two independent 64-block half-barriers
// h staging is the R10-exact block-wide cp.async pattern (proven 3x).
#define RS_H 0
#define RS_L 16640
#define HS_H 33280
#define HS_L 41600
#define RC_PITCH 520
#define RC_SMEM (49920 * 2 + (4608 + 128 + 32) * 4)   // 118,912 B
__global__ void __launch_bounds__(NT, 1) recurrence(
    const float* __restrict__ brz, const float* __restrict__ bri,
    const float* __restrict__ brf, const float* __restrict__ bro)
{
    extern __shared__ __nv_bfloat16 smb[];
    float* red = (float*)(smb + 49920);   // [8][32][18] partials
    float* csm = red + 4608;              // 128 cell states
    float* brs = csm + 128;               // 32 biases (p = g*8+c)
    const uint32_t sbb = smem_u32(smb);

    const int tid = threadIdx.x;
    const int bid = blockIdx.x;
    const int jc  = (bid >> 1) * 8;
    const int b0g = (bid & 1) * 16;
    const int half = (bid & 1) * 32;      // barrier slot (128B spread)
    const int w = tid >> 5, lane = tid & 31;

    __shared__ unsigned s_base;
    if (tid == 0) s_base = g_gen2[half];  // consistent per-half snapshot

    // Stage R (32 rows m=g*8+c -> global n=g*512+jc+c), hi+lo, pitch 520.
    for (int i = 0; i < 16; i++) {
        const int idx = i * 256 + tid;            // 4096 uint4 total
        const int part = idx >> 11, rest = idx & 2047;
        const int m = rest >> 6, u = rest & 63;
        const int n = (m >> 3) * 512 + jc + (m & 7);
        const uint4 v = *((const uint4*)(part ? g_Rl : g_Rh) + (size_t)n * 64 + u);
        *(uint4*)(smb + (part ? RS_L : RS_H) + m * RC_PITCH + u * 8) = v;
    }
    if (tid < 32) {
        const int g = tid >> 3, c = tid & 7;
        const float* bg = (g == 0) ? brz : (g == 1) ? bri : (g == 2) ? brf : bro;
        brs[tid] = bg[jc + c];
    }
    if (tid < 128) csm[tid] = 0.0f;
    __syncthreads();
    const unsigned base = s_base;

    // ldmatrix lane-address components
    const int arow = (lane & 15) * RC_PITCH;
    const int akad = (lane >> 4) << 3;
    const int brow = (((lane >> 4) & 1) * 8 + (lane & 7)) * RC_PITCH;
    const int bkad = ((lane >> 3) & 1) * 8;
    // cell roles (threads 0..127)
    const int c_ = (tid >> 4) & 7;    // hcol 0..7
    const int b_ = tid & 15;          // batch 0..15
    const int grp = lane >> 2, qp = lane & 3;

    // Hoist A(R) fragments: static smem -> registers, once for all steps.
    uint32_t AH0[4][4], AH1[4][4], AL0[4][4], AL1[4][4];
#pragma unroll
    for (int ks = 0; ks < 4; ks++) {
        const int kb = w * 64 + ks * 16;
        ldsm4(AH0[ks], sbb + 2 * (RS_H + arow + kb + akad));
        ldsm4(AH1[ks], sbb + 2 * (RS_H + 16 * RC_PITCH + arow + kb + akad));
        ldsm4(AL0[ks], sbb + 2 * (RS_L + arow + kb + akad));
        ldsm4(AL1[ks], sbb + 2 * (RS_L + 16 * RC_PITCH + arow + kb + akad));
    }

    // G prefetch for s = 0 (threads 0..127)
    float gv0 = 0.f, gv1 = 0.f, gv2 = 0.f, gv3 = 0.f;
    if (tid < 128) {
        gv0 = g_G[(0 * 512 + jc + c_) * BB + b0g + b_];
        gv1 = g_G[(1 * 512 + jc + c_) * BB + b0g + b_];
        gv2 = g_G[(2 * 512 + jc + c_) * BB + b0g + b_];
        gv3 = g_G[(3 * 512 + jc + c_) * BB + b0g + b_];
    }

    float histv = 0.0f;
    int   hist_idx = -1;

    for (int s = 0; s < SS; ++s) {
        // Stage h (bf16 hi/lo, 16 b-rows x 512 k, pitch 520) via cp.async.
        if (s == 0) {
            const uint4 z4 = make_uint4(0, 0, 0, 0);
#pragma unroll
            for (int i = 0; i < 8; i++) {
                const int idx = i * 256 + tid;        // 2048 uint4
                const int part = idx >> 10, rest = idx & 1023;
                const int r = rest >> 6, u = rest & 63;
                *(uint4*)(smb + (part ? HS_L : HS_H) + r * RC_PITCH + u * 8) = z4;
            }
        } else {
            const int pb = (s - 1) & 1;
            const uint4* hsrc = (const uint4*)g_hbf;
#pragma unroll
            for (int i = 0; i < 8; i++) {
                const int idx = i * 256 + tid;
                const int part = idx >> 10, rest = idx & 1023;
                const int r = rest >> 6, u = rest & 63;
                cpa16(sbb + 2 * (uint32_t)((part ? HS_L : HS_H) + r * RC_PITCH + u * 8),
                      hsrc + ((size_t)((pb * 2 + part) * 32 + b0g + r)) * 64 + u);
            }
            cpa_commit();
            cpa_wait0();
        }
        __syncthreads();

        // MMA: warp w covers k in [w*64, w*64+64), 4 k-steps of 16.
        float acc[2][2][4];
#pragma unroll
        for (int mi = 0; mi < 2; mi++)
#pragma unroll
            for (int ni = 0; ni < 2; ni++)
#pragma unroll
                for (int r = 0; r < 4; r++) acc[mi][ni][r] = 0.0f;

#pragma unroll
        for (int ks = 0; ks < 4; ks++) {
            const int kb = w * 64 + ks * 16;
            uint32_t Bh[4], Bl[4];
            ldsm4(Bh, sbb + 2 * (HS_H + brow + kb + bkad));
            ldsm4(Bl, sbb + 2 * (HS_L + brow + kb + bkad));
            mma_bf16(acc[0][0], AH0[ks], Bh);     mma_bf16(acc[0][1], AH0[ks], Bh + 2);
            mma_bf16(acc[1][0], AH1[ks], Bh);     mma_bf16(acc[1][1], AH1[ks], Bh + 2);
            mma_bf16(acc[0][0], AH0[ks], Bl);     mma_bf16(acc[0][1], AH0[ks], Bl + 2);
            mma_bf16(acc[1][0], AH1[ks], Bl);     mma_bf16(acc[1][1], AH1[ks], Bl + 2);
            mma_bf16(acc[0][0], AL0[ks], Bh);     mma_bf16(acc[0][1], AL0[ks], Bh + 2);
            mma_bf16(acc[1][0], AL1[ks], Bh);     mma_bf16(acc[1][1], AL1[ks], Bh + 2);
        }

        // Partials -> red[w][n=0..31][b=0..15] pitch 18
#pragma unroll
        for (int mi = 0; mi < 2; mi++)
#pragma unroll
            for (int ni = 0; ni < 2; ni++) {
                const int row = mi * 16 + grp;
                const int col = ni * 8 + qp * 2;
                *(float2*)&red[(w * 32 + row) * 18 + col] =
                    make_float2(acc[mi][ni][0], acc[mi][ni][1]);
                *(float2*)&red[(w * 32 + row + 8) * 18 + col] =
                    make_float2(acc[mi][ni][2], acc[mi][ni][3]);
            }
        __syncthreads();

        // Gate phase (threads 0..127): cell (hcol c_, batch b_).
        if (tid < 128) {
            float pz = gv0 + brs[0 + c_];
            float pi_ = gv1 + brs[8 + c_];
            float pf = gv2 + brs[16 + c_];
            float po = gv3 + brs[24 + c_];
#pragma unroll
            for (int q = 0; q < 8; q++) {
                pz  += red[(q * 32 + 0 + c_) * 18 + b_];
                pi_ += red[(q * 32 + 8 + c_) * 18 + b_];
                pf  += red[(q * 32 + 16 + c_) * 18 + b_];
                po  += red[(q * 32 + 24 + c_) * 18 + b_];
            }
            const float z  = tanhf(pz);
            const float iv = sigf(pi_);
            const float f  = sigf(pf);
            const float o  = sigf(po);
            const float cc = fmaf(f, csm[tid], z * iv);
            csm[tid] = cc;
            const float h = o * tanhf(cc);
            const __nv_bfloat16 hh = __float2bfloat16_rn(h);
            const __nv_bfloat16 hl = __float2bfloat16_rn(h - __bfloat162float(hh));
            g_hbf[s & 1][0][b0g + b_][jc + c_] = hh;
            g_hbf[s & 1][1][b0g + b_][jc + c_] = hl;
            histv = h;
            hist_idx = (s >= SS / 2)
                     ? (int)(((size_t)(s - SS / 2) * BB + b0g + b_) * HH + jc + c_)
                     : -1;
        }

        // Prefetch next G, per-half grid barrier (64 blocks), deferred Hist.
        if (s < SS - 1) {
            float t0 = 0.f, t1 = 0.f, t2 = 0.f, t3 = 0.f;
            if (tid < 128) {
                const float* Gn = g_G + (size_t)(s + 1) * (2048 * BB);
                t0 = Gn[(0 * 512 + jc + c_) * BB + b0g + b_];
                t1 = Gn[(1 * 512 + jc + c_) * BB + b0g + b_];
                t2 = Gn[(2 * 512 + jc + c_) * BB + b0g + b_];
                t3 = Gn[(3 * 512 + jc + c_) * BB + b0g + b_];
            }
            __threadfence();
            __syncthreads();
            if (tid == 0) {
                const unsigned tgt = base + (unsigned)s + 1u;
                if (atomicAdd(&g_cnt2[half], 1u) == 63u) {
                    // All 64 same-half blocks arrived; others spin on gen.
                    atomicExch(&g_cnt2[half], 0u);
                    __threadfence();
                    g_gen2[half] = tgt;
                } else {
                    while ((int)(g_gen2[half] - tgt) < 0) __nanosleep(32);
                    __threadfence();
                }
            }
            __syncthreads();
            if (hist_idx >= 0) g_Hist[hist_idx] = histv;
            gv0 = t0; gv1 = t1; gv2 = t2; gv3 = t3;
        } else {
            if (hist_idx >= 0) g_Hist[hist_idx] = histv;
        }
    }
    // Exit state: g_cnt2[*] == 0, g_gen2[half] == base + SS - 1 (replay-safe).
}

// ---------------------------------------------------------------------------
// Output GEMM: out[b][s'][o] = Hist[s'][b][:] . Wl[o][:] + bl[o]  (fp32)
__global__ void __launch_bounds__(256, 2) output_gemm(
    const float* __restrict__ Wl, const float* __restrict__ bl,
    float* __restrict__ out)
{
    constexpr int BM = 128, BN = 128, BK = 8;
    __shared__ float As[BK][BM + 4];
    __shared__ float Bs[BK][BN + 4];

    const int bx = blockIdx.x;
    const int by = blockIdx.y;
    const int m0 = by * BM;
    const int n0g = bx * BN;

    const int tid  = threadIdx.x;
    const int arow = tid >> 1, acol = (tid & 1) * 4;
    const int brow = tid >> 1, bcol = (tid & 1) * 4;
    const int tx = tid & 15, ty = tid >> 4;

    const float* apk = g_Hist + (size_t)(m0 + arow) * HH + acol;
    const float* bpk = Wl + (size_t)(n0g + brow) * HH + bcol;

    unsigned long long acc2[8][4];
#pragma unroll
    for (int i = 0; i < 8; i++)
#pragma unroll
        for (int j = 0; j < 4; j++) acc2[i][j] = 0ULL;

    float4 av = *(const float4*)(apk);
    float4 bv = *(const float4*)(bpk);

    for (int k0 = 0; k0 < HH; k0 += BK) {
        As[acol + 0][arow] = av.x; As[acol + 1][arow] = av.y;
        As[acol + 2][arow] = av.z; As[acol + 3][arow] = av.w;
        Bs[bcol + 0][brow] = bv.x; Bs[bcol + 1][brow] = bv.y;
        Bs[bcol + 2][brow] = bv.z; Bs[bcol + 3][brow] = bv.w;
        __syncthreads();
        if (k0 + BK < HH) {
            av = *(const float4*)(apk + k0 + BK);
            bv = *(const float4*)(bpk + k0 + BK);
        }
#pragma unroll
        for (int k = 0; k < BK; k++) {
            float ra[8];
            *(float4*)(ra)     = *(const float4*)(&As[k][4 * ty]);
            *(float4*)(ra + 4) = *(const float4*)(&As[k][64 + 4 * ty]);
            const ulonglong2 b01 = *(const ulonglong2*)(&Bs[k][4 * tx]);
            const ulonglong2 b23 = *(const ulonglong2*)(&Bs[k][64 + 4 * tx]);
#pragma unroll
            for (int i = 0; i < 8; i++) {
                const unsigned long long a2 = splat2(ra[i]);
                ffma2(acc2[i][0], a2, b01.x);
                ffma2(acc2[i][1], a2, b01.y);
                ffma2(acc2[i][2], a2, b23.x);
                ffma2(acc2[i][3], a2, b23.y);
            }
        }
        __syncthreads();
    }

    float acc[8][8];
#pragma unroll
    for (int i = 0; i < 8; i++)
#pragma unroll
        for (int jp = 0; jp < 4; jp++) {
            float2 f = unpack2(acc2[i][jp]);
            acc[i][2 * jp] = f.x; acc[i][2 * jp + 1] = f.y;
        }

#pragma unroll
    for (int i = 0; i < 8; i++) {
        const int m = m0 + (i >> 2) * 64 + 4 * ty + (i & 3);
        const int sp = m >> 5, bB = m & 31;
#pragma unroll
        for (int jh = 0; jh < 2; jh++) {
            const int n = n0g + jh * 64 + 4 * tx;
            float4 v = make_float4(acc[i][jh * 4 + 0] + bl[n + 0],
                                   acc[i][jh * 4 + 1] + bl[n + 1],
                                   acc[i][jh * 4 + 2] + bl[n + 2],
                                   acc[i][jh * 4 + 3] + bl[n + 3]);
            *(float4*)(out + ((size_t)bB * (SS / 2) + sp) * II + n) = v;
        }
    }
}

// ---------------------------------------------------------------------------
extern "C" void kernel_launch(void* const* d_in, const int* in_sizes, int n_in,
                              void* d_out, int out_size)
{
    const float* x   = (const float*)d_in[0];
    const float* Wz  = (const float*)d_in[1];  const float* bz  = (const float*)d_in[2];
    const float* Wi  = (const float*)d_in[3];  const float* bi  = (const float*)d_in[4];
    const float* Wf  = (const float*)d_in[5];  const float* bf  = (const float*)d_in[6];
    const float* Wo  = (const float*)d_in[7];  const float* bo  = (const float*)d_in[8];
    const float* Rz  = (const float*)d_in[9];  const float* brz = (const float*)d_in[10];
    const float* Ri  = (const float*)d_in[11]; const float* bri = (const float*)d_in[12];
    const float* Rf  = (const float*)d_in[13]; const float* brf = (const float*)d_in[14];
    const float* Ro  = (const float*)d_in[15]; const float* bro = (const float*)d_in[16];
    const float* Wl  = (const float*)d_in[17]; const float* bl  = (const float*)d_in[18];
    float* out = (float*)d_out;

    // 0) Convert x/W/R to bf16 hi/lo
    convert_prepass<<<592, 256>>>(x, Wz, Wi, Wf, Wo, Rz, Ri, Rf, Ro);

    // 1) Tensor-core (HMMA) input projections -> g_G
    cudaFuncSetAttribute(input_gemm_tc, cudaFuncAttributeMaxDynamicSharedMemorySize, IG_SMEM);
    input_gemm_tc<<<dim3(16, 256), 256, IG_SMEM>>>(bz, bi, bf, bo);

    // 2) Tensor-core persistent recurrence -> g_Hist
    cudaFuncSetAttribute(recurrence, cudaFuncAttributeMaxDynamicSharedMemorySize, RC_SMEM);
    recurrence<<<NB, NT, RC_SMEM>>>(brz, bri, brf, bro);

    // 3) Output projection -> d_out
    output_gemm<<<dim3(4, 128), 256>>>(Wl, bl, out);
}